// round 1
// baseline (speedup 1.0000x reference)
#include <cuda_runtime.h>
#include <math.h>

#define BB   64
#define NN   4096
#define DD   64
#define HH   256
#define SS   1024
#define TOT  49152   // 3 * D * H

// scratch: raw then normalized hypernet weights per batch
__device__ float g_params[BB * (size_t)TOT];

// ---------------- packed f32x2 helpers ----------------
__device__ __forceinline__ unsigned long long splat2(float a) {
    unsigned long long r;
    asm("mov.b64 %0, {%1, %1};" : "=l"(r) : "f"(a));
    return r;
}
__device__ __forceinline__ unsigned long long ffma2(unsigned long long a,
                                                    unsigned long long b,
                                                    unsigned long long c) {
    unsigned long long d;
    asm("fma.rn.f32x2 %0, %1, %2, %3;" : "=l"(d) : "l"(a), "l"(b), "l"(c));
    return d;
}
__device__ __forceinline__ float2 unpk(unsigned long long v) {
    float2 f;
    asm("mov.b64 {%0, %1}, %2;" : "=f"(f.x), "=f"(f.y) : "l"(v));
    return f;
}

// ---------------- kernel 1: hypernet GEMM ----------------
// mlp[b][n] = sum_k s[b][k] * W[k][n] + bias[n]
// M=64 (whole), block N-tile=128, K-tile=16. 256 threads: tx(0..31)->4 cols, ty(0..7)->8 rows.
__global__ __launch_bounds__(256) void k1_hypernet(const float* __restrict__ s,
                                                   const float* __restrict__ W,
                                                   const float* __restrict__ bias) {
    __shared__ float sA[16][64];    // [k][m]
    __shared__ float sB[16][128];   // [k][n]
    const int n0  = blockIdx.x * 128;
    const int tid = threadIdx.x;
    const int tx  = tid & 31, ty = tid >> 5;
    const int c0  = tx * 4, r0 = ty * 8;

    unsigned long long acc[8][2];
    #pragma unroll
    for (int i = 0; i < 8; i++) { acc[i][0] = 0ull; acc[i][1] = 0ull; }

    for (int k0 = 0; k0 < SS; k0 += 16) {
        // A chunk: 64 rows x 16 k
        {
            int m = tid >> 2, kk = (tid & 3) * 4;
            float4 a4 = *(const float4*)(s + (size_t)m * SS + k0 + kk);
            sA[kk + 0][m] = a4.x; sA[kk + 1][m] = a4.y;
            sA[kk + 2][m] = a4.z; sA[kk + 3][m] = a4.w;
        }
        // B chunk: 16 k x 128 n
        #pragma unroll
        for (int t = 0; t < 2; t++) {
            int idx = t * 256 + tid;
            int kk = idx >> 5, c4 = (idx & 31) * 4;
            *(float4*)(&sB[kk][c4]) =
                *(const float4*)(W + (size_t)(k0 + kk) * TOT + n0 + c4);
        }
        __syncthreads();
        #pragma unroll
        for (int kk = 0; kk < 16; kk++) {
            ulonglong2 bp = *(const ulonglong2*)(&sB[kk][c0]);   // 2 col-pairs
            float4 a0 = *(const float4*)(&sA[kk][r0]);
            float4 a1 = *(const float4*)(&sA[kk][r0 + 4]);
            unsigned long long s0 = splat2(a0.x), s1 = splat2(a0.y),
                               s2 = splat2(a0.z), s3 = splat2(a0.w),
                               s4 = splat2(a1.x), s5 = splat2(a1.y),
                               s6 = splat2(a1.z), s7 = splat2(a1.w);
            acc[0][0] = ffma2(s0, bp.x, acc[0][0]); acc[0][1] = ffma2(s0, bp.y, acc[0][1]);
            acc[1][0] = ffma2(s1, bp.x, acc[1][0]); acc[1][1] = ffma2(s1, bp.y, acc[1][1]);
            acc[2][0] = ffma2(s2, bp.x, acc[2][0]); acc[2][1] = ffma2(s2, bp.y, acc[2][1]);
            acc[3][0] = ffma2(s3, bp.x, acc[3][0]); acc[3][1] = ffma2(s3, bp.y, acc[3][1]);
            acc[4][0] = ffma2(s4, bp.x, acc[4][0]); acc[4][1] = ffma2(s4, bp.y, acc[4][1]);
            acc[5][0] = ffma2(s5, bp.x, acc[5][0]); acc[5][1] = ffma2(s5, bp.y, acc[5][1]);
            acc[6][0] = ffma2(s6, bp.x, acc[6][0]); acc[6][1] = ffma2(s6, bp.y, acc[6][1]);
            acc[7][0] = ffma2(s7, bp.x, acc[7][0]); acc[7][1] = ffma2(s7, bp.y, acc[7][1]);
        }
        __syncthreads();
    }
    float4 bv = *(const float4*)(bias + n0 + c0);
    #pragma unroll
    for (int i = 0; i < 8; i++) {
        float2 p0 = unpk(acc[i][0]), p1 = unpk(acc[i][1]);
        float4 o = make_float4(p0.x + bv.x, p0.y + bv.y, p1.x + bv.z, p1.y + bv.w);
        *(float4*)(g_params + (size_t)(r0 + i) * TOT + n0 + c0) = o;
    }
}

// ---------------- kernel 2: in-place L2 normalization ----------------
__global__ __launch_bounds__(256) void k2_normalize() {
    const int b   = blockIdx.x;
    const int tid = threadIdx.x;
    float* P = g_params + (size_t)b * TOT;

    // fc1 gate + value: [D][H] layout, norm over d (column h = tid)
    #pragma unroll
    for (int m = 0; m < 2; m++) {
        float* base = P + m * (DD * HH);
        float ss = 0.f;
        #pragma unroll 8
        for (int d = 0; d < DD; d++) { float v = base[d * HH + tid]; ss += v * v; }
        float inv = 1.f / fmaxf(sqrtf(ss), 1e-12f);
        #pragma unroll 8
        for (int d = 0; d < DD; d++) base[d * HH + tid] *= inv;
    }
    // fc2: [H][D] layout, norm over h (column d)
    __shared__ float part[4][64];
    __shared__ float invf[64];
    {
        float* base = P + 2 * (DD * HH);
        int dd = tid & 63, q = tid >> 6;
        float ss = 0.f;
        #pragma unroll 8
        for (int h = q * 64; h < q * 64 + 64; h++) { float v = base[h * DD + dd]; ss += v * v; }
        part[q][dd] = ss;
        __syncthreads();
        if (tid < 64) {
            float t = part[0][tid] + part[1][tid] + part[2][tid] + part[3][tid];
            invf[tid] = 1.f / fmaxf(sqrtf(t), 1e-12f);
        }
        __syncthreads();
        for (int i = tid; i < HH * DD; i += 256) base[i] *= invf[i & 63];
    }
}

// ---------------- kernel 3: fused RMSNorm + GLU MLP + residual ----------------
// grid (16, 64): blockIdx.y = batch, blockIdx.x -> 256 rows. 8 warps cooperate on
// groups of 8 rows. Weights resident in smem (fp32, 192 KB).
#define SMEM3_FLOATS (3 * DD * HH + DD * 8 + HH * 8 + 8 * 512)
#define SMEM3_BYTES  (SMEM3_FLOATS * 4)

__global__ __launch_bounds__(256) void k3_main(const float* __restrict__ x,
                                               const float* __restrict__ scale,
                                               float* __restrict__ out) {
    extern __shared__ float sm[];
    float* sWg  = sm;                  // [64][256]
    float* sWv  = sWg + DD * HH;       // [64][256]
    float* sWf  = sWv + DD * HH;       // [256][64]
    float* xT   = sWf + HH * DD;       // [d][8]
    float* hT   = xT + DD * 8;         // [h][8]
    float* pbuf = hT + HH * 8;         // [8][512]

    const int b    = blockIdx.y;
    const int nb0  = blockIdx.x * 256;
    const int tid  = threadIdx.x;
    const int w    = tid >> 5, lane = tid & 31;

    // preload normalized weights for this batch
    const float* P = g_params + (size_t)b * TOT;
    #pragma unroll 8
    for (int i = tid; i < TOT / 4; i += 256)
        ((float4*)sm)[i] = ((const float4*)P)[i];

    const float sc0 = scale[lane], sc1 = scale[lane + 32];
    __syncthreads();

    const float* xb = x + (size_t)b * NN * DD;

    for (int g = 0; g < 32; g++) {
        const int nb = nb0 + g * 8;

        // ---- phase A: RMSNorm, warp w handles row nb+w ----
        {
            const float* xr = xb + (size_t)(nb + w) * DD;
            float x0 = xr[lane], x1 = xr[lane + 32];
            float ssq = x0 * x0 + x1 * x1;
            #pragma unroll
            for (int o = 16; o > 0; o >>= 1) ssq += __shfl_xor_sync(0xffffffffu, ssq, o);
            float rr = rsqrtf(ssq * (1.0f / 64.0f) + 1e-6f);
            xT[lane * 8 + w]        = x0 * rr * sc0;
            xT[(lane + 32) * 8 + w] = x1 * rr * sc1;
        }
        __syncthreads();

        // ---- phase B: fc1 gate/value for h = w*32+lane over 8 rows ----
        {
            const int h = (w << 5) + lane;
            unsigned long long ag[4] = {0,0,0,0}, av[4] = {0,0,0,0};
            #pragma unroll 8
            for (int d = 0; d < DD; d++) {
                unsigned long long wg = splat2(sWg[d * HH + h]);
                unsigned long long wv = splat2(sWv[d * HH + h]);
                ulonglong2 xa = *(const ulonglong2*)(xT + d * 8);      // rows 0-3
                ulonglong2 xc = *(const ulonglong2*)(xT + d * 8 + 4);  // rows 4-7
                ag[0] = ffma2(xa.x, wg, ag[0]); ag[1] = ffma2(xa.y, wg, ag[1]);
                ag[2] = ffma2(xc.x, wg, ag[2]); ag[3] = ffma2(xc.y, wg, ag[3]);
                av[0] = ffma2(xa.x, wv, av[0]); av[1] = ffma2(xa.y, wv, av[1]);
                av[2] = ffma2(xc.x, wv, av[2]); av[3] = ffma2(xc.y, wv, av[3]);
            }
            float hv[8];
            #pragma unroll
            for (int p = 0; p < 4; p++) {
                float2 gg = unpk(ag[p]); float2 vv = unpk(av[p]);
                float e0 = __expf(-gg.x), e1 = __expf(-gg.y);
                hv[2 * p]     = gg.x * __fdividef(1.f, 1.f + e0) * vv.x;
                hv[2 * p + 1] = gg.y * __fdividef(1.f, 1.f + e1) * vv.y;
            }
            float4* hp = (float4*)(hT + h * 8);
            hp[0] = make_float4(hv[0], hv[1], hv[2], hv[3]);
            hp[1] = make_float4(hv[4], hv[5], hv[6], hv[7]);
        }
        __syncthreads();

        // ---- phase C: fc2 partials, warp w sums h in [w*32, w*32+32) ----
        {
            unsigned long long o0[4] = {0,0,0,0}, o1[4] = {0,0,0,0};
            const int hbase = w << 5;
            #pragma unroll 8
            for (int hh = 0; hh < 32; hh++) {
                const int h = hbase + hh;
                ulonglong2 ha = *(const ulonglong2*)(hT + h * 8);
                ulonglong2 hc = *(const ulonglong2*)(hT + h * 8 + 4);
                unsigned long long w0 = splat2(sWf[h * DD + lane]);
                unsigned long long w1 = splat2(sWf[h * DD + lane + 32]);
                o0[0] = ffma2(ha.x, w0, o0[0]); o0[1] = ffma2(ha.y, w0, o0[1]);
                o0[2] = ffma2(hc.x, w0, o0[2]); o0[3] = ffma2(hc.y, w0, o0[3]);
                o1[0] = ffma2(ha.x, w1, o1[0]); o1[1] = ffma2(ha.y, w1, o1[1]);
                o1[2] = ffma2(hc.x, w1, o1[2]); o1[3] = ffma2(hc.y, w1, o1[3]);
            }
            float* pb = pbuf + w * 512;
            #pragma unroll
            for (int p = 0; p < 4; p++) {
                float2 a = unpk(o0[p]); float2 c = unpk(o1[p]);
                pb[(2 * p) * 64 + lane]          = a.x;
                pb[(2 * p + 1) * 64 + lane]      = a.y;
                pb[(2 * p) * 64 + lane + 32]     = c.x;
                pb[(2 * p + 1) * 64 + lane + 32] = c.y;
            }
        }
        __syncthreads();

        // ---- reduce partials + residual + store ----
        {
            float* ob = out + ((size_t)b * NN + nb) * DD;
            const float* xr = xb + (size_t)nb * DD;
            #pragma unroll
            for (int t = 0; t < 2; t++) {
                int o = t * 256 + tid;
                float sum = 0.f;
                #pragma unroll
                for (int ww = 0; ww < 8; ww++) sum += pbuf[ww * 512 + o];
                ob[o] = sum + xr[o];
            }
        }
        __syncthreads();
    }
}

// ---------------- launch ----------------
extern "C" void kernel_launch(void* const* d_in, const int* in_sizes, int n_in,
                              void* d_out, int out_size) {
    const float* x     = (const float*)d_in[0];
    const float* s     = (const float*)d_in[1];
    const float* W     = (const float*)d_in[2];
    const float* bias  = (const float*)d_in[3];
    const float* scale = (const float*)d_in[4];
    float* out = (float*)d_out;

    k1_hypernet<<<dim3(TOT / 128), 256>>>(s, W, bias);
    k2_normalize<<<dim3(BB), 256>>>();

    cudaFuncSetAttribute(k3_main, cudaFuncAttributeMaxDynamicSharedMemorySize, SMEM3_BYTES);
    k3_main<<<dim3(NN / 256, BB), 256, SMEM3_BYTES>>>(x, scale, out);
}